// round 8
// baseline (speedup 1.0000x reference)
#include <cuda_runtime.h>

#define ORDER 128
#define SEQN  16384
#define NB    64
#define LTAP  192
#define TILE  512
#define NTHR  128

// ---------------- scratch (device globals; no allocation) ----------------
__device__ float      g_P[2][ORDER * ORDER];       // ping-pong powers of A
__device__ float      g_V[LTAP * ORDER * 7];       // V[j][r][c] = (A^j [B|x0])[r][c], c<7
__device__ ulonglong2 g_H2[LTAP * 9];              // packed taps per m: 18 u64 = (h[2p][i],h[2p+1][i])
__device__ float      g_S[LTAP * 6];               // s_k = C A^k x0

// ---------------- precompute kernels ----------------
__global__ void k_init(const float* __restrict__ A, const float* __restrict__ B,
                       const float* __restrict__ x0) {
    int tid = blockIdx.x * blockDim.x + threadIdx.x;
    if (tid < ORDER * ORDER) g_P[0][tid] = A[tid];
    if (tid < ORDER * 7) {
        int r = tid / 7, c = tid % 7;
        g_V[tid] = (c < 6) ? B[r * 6 + c] : x0[r];
    }
}

// V[m + j] = P @ V[j] for j in [0, nj); optionally P' = P @ P
__global__ void k_double(int m, int nj, int pi, int dosq) {
    int Nv = nj * ORDER * 7;
    int N  = Nv + (dosq ? ORDER * ORDER : 0);
    int tid = blockIdx.x * blockDim.x + threadIdx.x;
    if (tid >= N) return;
    const float* __restrict__ P = g_P[pi];
    if (tid < Nv) {
        int j = tid / (ORDER * 7);
        int loc = tid % (ORDER * 7);
        int r = loc / 7, c = loc % 7;
        const float* vcol = g_V + j * (ORDER * 7) + c;
        const float* prow = P + r * ORDER;
        float s = 0.f;
        #pragma unroll 8
        for (int k = 0; k < ORDER; k++) s += prow[k] * vcol[k * 7];
        g_V[(m + j) * (ORDER * 7) + r * 7 + c] = s;
    } else {
        int t2 = tid - Nv;
        int r = t2 >> 7, c = t2 & 127;
        float s = 0.f;
        #pragma unroll 8
        for (int k = 0; k < ORDER; k++) s += P[r * ORDER + k] * P[k * ORDER + c];
        g_P[1 - pi][r * ORDER + c] = s;
    }
}

// taps h_m (h_0 = D, h_m = C A^{m-1} B) in pair layout, plus s_k = C A^k x0
__global__ void k_taps(const float* __restrict__ C, const float* __restrict__ D) {
    const int NH = LTAP * 36;
    const int N  = NH + LTAP * 6;
    int tid = blockIdx.x * blockDim.x + threadIdx.x;
    if (tid >= N) return;
    float* Hf = (float*)g_H2;
    if (tid < NH) {
        int mm = tid / 36, r36 = tid % 36;
        int o = r36 / 6, i = r36 % 6;
        float v;
        if (mm == 0) {
            v = D[o * 6 + i];
        } else {
            const float* vp = g_V + (mm - 1) * (ORDER * 7) + i;
            const float* cp = C + o * ORDER;
            v = 0.f;
            #pragma unroll 8
            for (int r = 0; r < ORDER; r++) v += cp[r] * vp[r * 7];
        }
        // u64 index n = i*3 + (o>>1); float index = n*2 + (o&1)
        Hf[mm * 36 + ((i * 3 + (o >> 1)) * 2 + (o & 1))] = v;
    } else {
        int t2 = tid - NH;
        int k = t2 / 6, o = t2 % 6;
        const float* cp = C + o * ORDER;
        const float* vp = g_V + k * (ORDER * 7) + 6;
        float v = 0.f;
        #pragma unroll 8
        for (int r = 0; r < ORDER; r++) v += cp[r] * vp[r * 7];
        g_S[k * 6 + o] = v;
    }
}

// ---------------- main convolution kernel ----------------
#define FMA2(acc, hh, uu) asm("fma.rn.f32x2 %0, %1, %2, %0;" : "+l"(acc) : "l"(hh), "l"(uu))
#define PACK2(d, f)  asm("mov.b64 %0, {%1, %1};" : "=l"(d) : "r"(__float_as_uint(f)))

__device__ __forceinline__ void unpk(unsigned long long v, float& a, float& b) {
    unsigned int lo, hi;
    asm("mov.b64 {%0, %1}, %2;" : "=r"(lo), "=r"(hi) : "l"(v));
    a = __uint_as_float(lo);
    b = __uint_as_float(hi);
}

#define LOADROW(Rn, p) do {                                   \
    PACK2(Rn##_0, (p)[0]); PACK2(Rn##_1, (p)[1]);             \
    PACK2(Rn##_2, (p)[2]); PACK2(Rn##_3, (p)[3]);             \
    PACK2(Rn##_4, (p)[4]); PACK2(Rn##_5, (p)[5]);             \
} while (0)

#define TAPI(h0, h1, h2, RA, RB, RC, RD, i) do {              \
    FMA2(a00, h0, RA##_##i); FMA2(a01, h1, RA##_##i); FMA2(a02, h2, RA##_##i); \
    FMA2(a10, h0, RB##_##i); FMA2(a11, h1, RB##_##i); FMA2(a12, h2, RB##_##i); \
    FMA2(a20, h0, RC##_##i); FMA2(a21, h1, RC##_##i); FMA2(a22, h2, RC##_##i); \
    FMA2(a30, h0, RD##_##i); FMA2(a31, h1, RD##_##i); FMA2(a32, h2, RD##_##i); \
} while (0)

#define STEP(hp, RA, RB, RC, RD) do {                         \
    ulonglong2 t0 = (hp)[0], t1 = (hp)[1], t2 = (hp)[2];      \
    TAPI(t0.x, t0.y, t1.x, RA, RB, RC, RD, 0);                \
    TAPI(t1.y, t2.x, t2.y, RA, RB, RC, RD, 1);                \
    ulonglong2 t3 = (hp)[3], t4 = (hp)[4], t5 = (hp)[5];      \
    TAPI(t3.x, t3.y, t4.x, RA, RB, RC, RD, 2);                \
    TAPI(t4.y, t5.x, t5.y, RA, RB, RC, RD, 3);                \
    ulonglong2 t6 = (hp)[6], t7 = (hp)[7], t8 = (hp)[8];      \
    TAPI(t6.x, t6.y, t7.x, RA, RB, RC, RD, 4);                \
    TAPI(t7.y, t8.x, t8.y, RA, RB, RC, RD, 5);                \
} while (0)

__global__ void __launch_bounds__(NTHR, 3) k_conv(
    const float* __restrict__ u,
    const float* __restrict__ imean, const float* __restrict__ istd,
    const float* __restrict__ omean, const float* __restrict__ ostd,
    float* __restrict__ out)
{
    __shared__ float      su[(TILE + LTAP) * 7];   // 704 rows, stride 7 (conflict padding)
    __shared__ ulonglong2 sh[LTAP * 9];            // packed taps (27648 B)

    const int tid = threadIdx.x;
    const int b  = blockIdx.y;
    const int k0 = blockIdx.x * TILE;

    // stage taps
    for (int idx = tid; idx < LTAP * 9; idx += NTHR) sh[idx] = g_H2[idx];

    // stage standardized input window: row sr <-> global k = k0 - LTAP + sr
    float im[6], rs[6];
    #pragma unroll
    for (int i = 0; i < 6; i++) { im[i] = imean[i]; rs[i] = 1.0f / istd[i]; }
    const float* ub = u + ((long long)b * SEQN) * 6;
    for (int idx = tid; idx < (TILE + LTAP) * 6; idx += NTHR) {
        int sr = idx / 6, i = idx - sr * 6;
        int k = k0 - LTAP + sr;
        float v = 0.f;
        if (k >= 0) v = (ub[k * 6 + i] - im[i]) * rs[i];
        su[sr * 7 + i] = v;
    }
    __syncthreads();

    const int kb = tid * 4;                       // local k offset of this thread's 4 outputs
    const float* up = su + (kb + LTAP) * 7;       // row for local k = kb (tap m = 0)

    unsigned long long r0_0, r0_1, r0_2, r0_3, r0_4, r0_5;
    unsigned long long r1_0, r1_1, r1_2, r1_3, r1_4, r1_5;
    unsigned long long r2_0, r2_1, r2_2, r2_3, r2_4, r2_5;
    unsigned long long r3_0, r3_1, r3_2, r3_3, r3_4, r3_5;
    unsigned long long a00 = 0, a01 = 0, a02 = 0, a10 = 0, a11 = 0, a12 = 0;
    unsigned long long a20 = 0, a21 = 0, a22 = 0, a30 = 0, a31 = 0, a32 = 0;

    LOADROW(r0, up);
    LOADROW(r1, up + 7);
    LOADROW(r2, up + 14);
    LOADROW(r3, up + 21);

    const ulonglong2* hpp = sh;
    #pragma unroll 1
    for (int it = 0; it < LTAP / 4; ++it) {
        STEP(hpp,      r0, r1, r2, r3);  LOADROW(r3, up - 7);
        STEP(hpp + 9,  r3, r0, r1, r2);  LOADROW(r2, up - 14);
        STEP(hpp + 18, r2, r3, r0, r1);  LOADROW(r1, up - 21);
        STEP(hpp + 27, r1, r2, r3, r0);  LOADROW(r0, up - 28);
        hpp += 36;
        up  -= 28;
    }

    // ---------------- epilogue ----------------
    const float os0 = ostd[0], os1 = ostd[1], os2 = ostd[2];
    const float os3 = ostd[3], os4 = ostd[4], os5 = ostd[5];
    const float om0 = omean[0], om1 = omean[1], om2 = omean[2];
    const float om3 = omean[3], om4 = omean[4], om5 = omean[5];
    const bool addinit = (k0 == 0);
    float* outp = out + ((long long)b * SEQN + (k0 + kb)) * 6;

#define EPI(j, A0, A1, A2) do {                                               \
    float y0, y1, y2, y3, y4, y5;                                             \
    unpk(A0, y0, y1); unpk(A1, y2, y3); unpk(A2, y4, y5);                     \
    if (addinit) {                                                            \
        int kk = kb + (j);                                                    \
        if (kk < LTAP) {                                                      \
            const float* sp = g_S + kk * 6;                                   \
            y0 += sp[0]; y1 += sp[1]; y2 += sp[2];                            \
            y3 += sp[3]; y4 += sp[4]; y5 += sp[5];                            \
        }                                                                     \
    }                                                                         \
    float* op = outp + (j) * 6;                                               \
    op[0] = fmaf(y0, os0, om0); op[1] = fmaf(y1, os1, om1);                   \
    op[2] = fmaf(y2, os2, om2); op[3] = fmaf(y3, os3, om3);                   \
    op[4] = fmaf(y4, os4, om4); op[5] = fmaf(y5, os5, om5);                   \
} while (0)

    EPI(0, a00, a01, a02);
    EPI(1, a10, a11, a12);
    EPI(2, a20, a21, a22);
    EPI(3, a30, a31, a32);
#undef EPI
}

// ---------------- launch ----------------
extern "C" void kernel_launch(void* const* d_in, const int* in_sizes, int n_in,
                              void* d_out, int out_size) {
    const float* inp   = (const float*)d_in[0];
    const float* A     = (const float*)d_in[1];
    const float* B     = (const float*)d_in[2];
    const float* C     = (const float*)d_in[3];
    const float* D     = (const float*)d_in[4];
    const float* x0    = (const float*)d_in[5];
    const float* imean = (const float*)d_in[6];
    const float* istd  = (const float*)d_in[7];
    const float* omean = (const float*)d_in[8];
    const float* ostd  = (const float*)d_in[9];
    float* out = (float*)d_out;

    k_init<<<64, 256>>>(A, B, x0);

    const int ms[8]  = {1, 2, 4, 8, 16, 32, 64, 128};
    const int njs[8] = {1, 2, 4, 8, 16, 32, 64, 64};
    int pi = 0;
    for (int s = 0; s < 8; s++) {
        int dosq = (s < 7) ? 1 : 0;
        int N = njs[s] * ORDER * 7 + (dosq ? ORDER * ORDER : 0);
        k_double<<<(N + 255) / 256, 256>>>(ms[s], njs[s], pi, dosq);
        if (dosq) pi ^= 1;
    }

    k_taps<<<(LTAP * 42 + 255) / 256, 256>>>(C, D);

    dim3 grid(SEQN / TILE, NB);
    k_conv<<<grid, NTHR>>>(inp, imean, istd, omean, ostd, out);
}